// round 3
// baseline (speedup 1.0000x reference)
#include <cuda_runtime.h>

#define NN   50000
#define NE   800000
#define CIN  64
#define HID  128
#define NL   4
#define LN_EPS 1e-5f

// ---------------- scratch (no allocations allowed) ----------------
__device__ float g_h[NN * HID];      // node features between layers
__device__ float g_m[NN * HID];      // h @ W per layer
__device__ float g_deg[NN];
__device__ float g_dinv[NN];
__device__ int   g_count[NN];
__device__ int   g_rowptr[NN + 1];
__device__ int   g_cursor[NN];
__device__ int   g_src[NE];          // CSR (by dst) source indices
__device__ float g_norm[NE];         // CSR edge norm coefficients

// ---------------- preprocessing ----------------
__global__ void init_kernel() {
    int i = blockIdx.x * blockDim.x + threadIdx.x;
    if (i < NN) { g_deg[i] = 1.0f; g_count[i] = 0; }   // self-loop weight 1
}

__global__ void edge_deg_kernel(const int* __restrict__ ei,
                                const float* __restrict__ w) {
    int e = blockIdx.x * blockDim.x + threadIdx.x;
    if (e >= NE) return;
    int d = ei[NE + e];
    atomicAdd(&g_deg[d], w[e]);
    atomicAdd(&g_count[d], 1);
}

__global__ void dinv_kernel() {
    int i = blockIdx.x * blockDim.x + threadIdx.x;
    if (i < NN) {
        float dg = g_deg[i];
        g_dinv[i] = (dg > 0.f) ? rsqrtf(dg) : 0.f;
    }
}

// single-block scan: per-thread chunk sums -> Hillis-Steele -> write prefixes
__global__ void scan_kernel() {
    __shared__ int sh[1024];
    const int CH = (NN + 1023) / 1024;   // 49
    int t = threadIdx.x;
    int start = t * CH;
    int s = 0;
    for (int i = 0; i < CH; i++) {
        int idx = start + i;
        if (idx < NN) s += g_count[idx];
    }
    sh[t] = s;
    __syncthreads();
    for (int off = 1; off < 1024; off <<= 1) {
        int v = (t >= off) ? sh[t - off] : 0;
        __syncthreads();
        sh[t] += v;
        __syncthreads();
    }
    int run = (t == 0) ? 0 : sh[t - 1];
    for (int i = 0; i < CH; i++) {
        int idx = start + i;
        if (idx < NN) {
            g_rowptr[idx] = run;
            g_cursor[idx] = run;
            run += g_count[idx];
        }
    }
    if (t == 1023) g_rowptr[NN] = sh[1023];
}

__global__ void fill_kernel(const int* __restrict__ ei,
                            const float* __restrict__ w) {
    int e = blockIdx.x * blockDim.x + threadIdx.x;
    if (e >= NE) return;
    int s = ei[e];
    int d = ei[NE + e];
    int p = atomicAdd(&g_cursor[d], 1);
    g_src[p]  = s;
    g_norm[p] = g_dinv[s] * w[e] * g_dinv[d];
}

// ---------------- GEMM core: C = A @ W, tile 32 rows x 128 cols ----------------
// block = 256 threads, K-tiles of 64.
// thread (cg,rg): cg=t&31 -> cols cg*4..cg*4+3, rg=t>>5 -> rows rg*4..rg*4+3
template <int K>
__device__ __forceinline__ void gemm_body(const float* __restrict__ A,
                                          const float* __restrict__ W,
                                          float4& acc0, float4& acc1,
                                          float4& acc2, float4& acc3) {
    __shared__ float xs[32][64];
    __shared__ float Ws[64][128];
    int t    = threadIdx.x;
    int row0 = blockIdx.x * 32;
    int cg   = t & 31;
    int rg   = t >> 5;

    for (int kt = 0; kt < K; kt += 64) {
        const float4* Wg  = (const float4*)(W + kt * 128);
        float4*       Wsv = (float4*)Ws;
        #pragma unroll
        for (int idx = 0; idx < 8; idx++)            // 8*256 = 2048 float4
            Wsv[t + idx * 256] = Wg[t + idx * 256];
        #pragma unroll
        for (int idx = 0; idx < 8; idx++) {          // 8*256 = 2048 floats
            int li = t + idx * 256;
            int r = li >> 6, k = li & 63;
            int row = row0 + r;
            xs[r][k] = (row < NN) ? A[row * K + kt + k] : 0.f;
        }
        __syncthreads();

        #pragma unroll 8
        for (int k = 0; k < 64; k++) {
            float4 w4 = *(const float4*)&Ws[k][cg * 4];
            float x0 = xs[rg * 4 + 0][k];
            float x1 = xs[rg * 4 + 1][k];
            float x2 = xs[rg * 4 + 2][k];
            float x3 = xs[rg * 4 + 3][k];
            acc0.x += x0 * w4.x; acc0.y += x0 * w4.y; acc0.z += x0 * w4.z; acc0.w += x0 * w4.w;
            acc1.x += x1 * w4.x; acc1.y += x1 * w4.y; acc1.z += x1 * w4.z; acc1.w += x1 * w4.w;
            acc2.x += x2 * w4.x; acc2.y += x2 * w4.y; acc2.z += x2 * w4.z; acc2.w += x2 * w4.w;
            acc3.x += x3 * w4.x; acc3.y += x3 * w4.y; acc3.z += x3 * w4.z; acc3.w += x3 * w4.w;
        }
        __syncthreads();
    }
}

// input projection: g_h = relu(x @ W_in + b_in)
__global__ void __launch_bounds__(256)
gemm_in_kernel(const float* __restrict__ A, const float* __restrict__ W,
               const float* __restrict__ bias) {
    float4 acc0 = {0,0,0,0}, acc1 = {0,0,0,0}, acc2 = {0,0,0,0}, acc3 = {0,0,0,0};
    gemm_body<CIN>(A, W, acc0, acc1, acc2, acc3);

    int t = threadIdx.x, cg = t & 31, rg = t >> 5;
    int row0 = blockIdx.x * 32;
    float4 b4 = ((const float4*)bias)[cg];
    float4 accs[4] = {acc0, acc1, acc2, acc3};
    #pragma unroll
    for (int i = 0; i < 4; i++) {
        int row = row0 + rg * 4 + i;
        if (row < NN) {
            float4 v = accs[i];
            v.x = fmaxf(v.x + b4.x, 0.f); v.y = fmaxf(v.y + b4.y, 0.f);
            v.z = fmaxf(v.z + b4.z, 0.f); v.w = fmaxf(v.w + b4.w, 0.f);
            ((float4*)g_h)[row * 32 + cg] = v;
        }
    }
}

// hidden layer GEMM: g_m = g_h @ conv_W[l]
__global__ void __launch_bounds__(256)
gemm_hid_kernel(const float* __restrict__ W) {
    float4 acc0 = {0,0,0,0}, acc1 = {0,0,0,0}, acc2 = {0,0,0,0}, acc3 = {0,0,0,0};
    gemm_body<HID>(g_h, W, acc0, acc1, acc2, acc3);

    int t = threadIdx.x, cg = t & 31, rg = t >> 5;
    int row0 = blockIdx.x * 32;
    float4 accs[4] = {acc0, acc1, acc2, acc3};
    #pragma unroll
    for (int i = 0; i < 4; i++) {
        int row = row0 + rg * 4 + i;
        if (row < NN)
            ((float4*)g_m)[row * 32 + cg] = accs[i];
    }
}

// ---------------- fused aggregation + bias + LN + relu + residual ----------------
// one warp per node; 4 cols per lane (float4). last!=0 -> write to `out`
__global__ void __launch_bounds__(128)
agg_ln_kernel(const float* __restrict__ cb, const float* __restrict__ lg,
              const float* __restrict__ lb, float* __restrict__ out, int last) {
    int warp = threadIdx.x >> 5;
    int lane = threadIdx.x & 31;
    int i = blockIdx.x * 4 + warp;
    if (i >= NN) return;

    const float4* m4 = (const float4*)g_m;
    float di = g_dinv[i];
    float sn = di * di;                       // self-loop norm
    float4 acc = m4[i * 32 + lane];
    acc.x *= sn; acc.y *= sn; acc.z *= sn; acc.w *= sn;

    int jb = g_rowptr[i], je = g_rowptr[i + 1];
    for (int j = jb; j < je; j++) {
        int   s  = g_src[j];
        float nw = g_norm[j];
        float4 v = m4[s * 32 + lane];
        acc.x += nw * v.x; acc.y += nw * v.y;
        acc.z += nw * v.z; acc.w += nw * v.w;
    }

    float4 b4 = ((const float4*)cb)[lane];
    acc.x += b4.x; acc.y += b4.y; acc.z += b4.z; acc.w += b4.w;

    float sum = acc.x + acc.y + acc.z + acc.w;
    #pragma unroll
    for (int o = 16; o; o >>= 1) sum += __shfl_xor_sync(0xFFFFFFFFu, sum, o);
    float mu = sum * (1.0f / 128.0f);

    float dx = acc.x - mu, dy = acc.y - mu, dz = acc.z - mu, dw = acc.w - mu;
    float vs = dx * dx + dy * dy + dz * dz + dw * dw;
    #pragma unroll
    for (int o = 16; o; o >>= 1) vs += __shfl_xor_sync(0xFFFFFFFFu, vs, o);
    float var = vs * (1.0f / 128.0f);
    float r = rsqrtf(var + LN_EPS);

    float4 g4  = ((const float4*)lg)[lane];
    float4 lb4 = ((const float4*)lb)[lane];
    float4 hres = ((const float4*)g_h)[i * 32 + lane];

    float4 o;
    o.x = fmaxf(dx * r * g4.x + lb4.x, 0.f) + hres.x;
    o.y = fmaxf(dy * r * g4.y + lb4.y, 0.f) + hres.y;
    o.z = fmaxf(dz * r * g4.z + lb4.z, 0.f) + hres.z;
    o.w = fmaxf(dw * r * g4.w + lb4.w, 0.f) + hres.w;

    if (last) ((float4*)out)[i * 32 + lane] = o;
    else      ((float4*)g_h)[i * 32 + lane] = o;
}

// ---------------- launch ----------------
extern "C" void kernel_launch(void* const* d_in, const int* in_sizes, int n_in,
                              void* d_out, int out_size) {
    const float* x      = (const float*)d_in[0];
    const int*   ei     = (const int*)d_in[1];      // int32 (JAX x64 disabled)
    const float* ew     = (const float*)d_in[2];
    const float* W_in   = (const float*)d_in[3];
    const float* b_in   = (const float*)d_in[4];
    const float* conv_W = (const float*)d_in[5];
    const float* conv_b = (const float*)d_in[6];
    const float* ln_g   = (const float*)d_in[7];
    const float* ln_b   = (const float*)d_in[8];
    float* out = (float*)d_out;

    const int TB = 256;
    int nb_n = (NN + TB - 1) / TB;
    int nb_e = (NE + TB - 1) / TB;

    // preprocessing: degree, dinv, CSR by dst
    init_kernel<<<nb_n, TB>>>();
    edge_deg_kernel<<<nb_e, TB>>>(ei, ew);
    dinv_kernel<<<nb_n, TB>>>();
    scan_kernel<<<1, 1024>>>();
    fill_kernel<<<nb_e, TB>>>(ei, ew);

    // input projection
    int gemm_blocks = (NN + 31) / 32;
    gemm_in_kernel<<<gemm_blocks, 256>>>(x, W_in, b_in);

    // layers
    int agg_blocks = (NN + 3) / 4;
    for (int l = 0; l < NL; l++) {
        gemm_hid_kernel<<<gemm_blocks, 256>>>(conv_W + l * HID * HID);
        agg_ln_kernel<<<agg_blocks, 128>>>(conv_b + l * HID, ln_g + l * HID,
                                           ln_b + l * HID, out, l == NL - 1);
    }
}

// round 4
// speedup vs baseline: 1.1827x; 1.1827x over previous
#include <cuda_runtime.h>

#define NN   50000
#define NE   800000
#define CIN  64
#define HID  128
#define NL   4
#define LN_EPS 1e-5f

#define SCAN_BLK 256
#define SCAN_NB  ((NN + SCAN_BLK - 1) / SCAN_BLK)   // 196

// ---------------- scratch (no allocations allowed) ----------------
__device__ float g_h[NN * HID];      // node features between layers
__device__ float g_m[NN * HID];      // h @ W per layer
__device__ float g_deg[NN];
__device__ float g_dinv[NN];
__device__ int   g_count[NN];
__device__ int   g_rowptr[NN + 1];
__device__ int   g_cursor[NN];
__device__ int   g_src[NE];          // CSR (by dst) source indices
__device__ float g_norm[NE];         // CSR edge norm coefficients
__device__ int   g_bsum[SCAN_NB];
__device__ int   g_boff[SCAN_NB];
__device__ int   g_total;

// ---------------- preprocessing ----------------
__global__ void init_kernel() {
    int i = blockIdx.x * blockDim.x + threadIdx.x;
    if (i < NN) { g_deg[i] = 1.0f; g_count[i] = 0; }   // self-loop weight 1
}

__global__ void edge_deg_kernel(const int* __restrict__ ei,
                                const float* __restrict__ w) {
    int e = blockIdx.x * blockDim.x + threadIdx.x;
    if (e >= NE) return;
    int d = ei[NE + e];
    atomicAdd(&g_deg[d], w[e]);
    atomicAdd(&g_count[d], 1);
}

__global__ void dinv_kernel() {
    int i = blockIdx.x * blockDim.x + threadIdx.x;
    if (i < NN) {
        float dg = g_deg[i];
        g_dinv[i] = (dg > 0.f) ? rsqrtf(dg) : 0.f;
    }
}

// ---- hierarchical scan: per-block scan -> block-sum scan -> add offsets ----
__global__ void __launch_bounds__(SCAN_BLK)
scan1_kernel() {
    int b = blockIdx.x, t = threadIdx.x;
    int idx = b * SCAN_BLK + t;
    int v = (idx < NN) ? g_count[idx] : 0;
    int lane = t & 31, w = t >> 5;
    int x = v;
    #pragma unroll
    for (int o = 1; o < 32; o <<= 1) {
        int y = __shfl_up_sync(0xFFFFFFFFu, x, o);
        if (lane >= o) x += y;
    }
    __shared__ int wsum[8];
    if (lane == 31) wsum[w] = x;
    __syncthreads();
    if (w == 0 && lane < 8) {
        int s = wsum[lane];
        #pragma unroll
        for (int o = 1; o < 8; o <<= 1) {
            int y = __shfl_up_sync(0xFFu, s, o);
            if (lane >= o) s += y;
        }
        wsum[lane] = s;
    }
    __syncthreads();
    int incl = x + ((w > 0) ? wsum[w - 1] : 0);
    if (idx < NN) g_rowptr[idx] = incl - v;   // block-local exclusive prefix
    if (t == SCAN_BLK - 1) g_bsum[b] = incl;
}

__global__ void __launch_bounds__(SCAN_BLK)
scan2_kernel() {
    int t = threadIdx.x;
    int lane = t & 31, w = t >> 5;
    int v = (t < SCAN_NB) ? g_bsum[t] : 0;
    int x = v;
    #pragma unroll
    for (int o = 1; o < 32; o <<= 1) {
        int y = __shfl_up_sync(0xFFFFFFFFu, x, o);
        if (lane >= o) x += y;
    }
    __shared__ int wsum[8];
    if (lane == 31) wsum[w] = x;
    __syncthreads();
    if (w == 0 && lane < 8) {
        int s = wsum[lane];
        #pragma unroll
        for (int o = 1; o < 8; o <<= 1) {
            int y = __shfl_up_sync(0xFFu, s, o);
            if (lane >= o) s += y;
        }
        wsum[lane] = s;
    }
    __syncthreads();
    int incl = x + ((w > 0) ? wsum[w - 1] : 0);
    if (t < SCAN_NB) g_boff[t] = incl - v;    // exclusive
    if (t == SCAN_BLK - 1) g_total = incl;
}

__global__ void __launch_bounds__(SCAN_BLK)
scan3_kernel() {
    int idx = blockIdx.x * SCAN_BLK + threadIdx.x;
    if (idx < NN) {
        int r = g_rowptr[idx] + g_boff[idx >> 8];
        g_rowptr[idx] = r;
        g_cursor[idx] = r;
    }
    if (idx == 0) g_rowptr[NN] = g_total;
}

__global__ void fill_kernel(const int* __restrict__ ei,
                            const float* __restrict__ w) {
    int e = blockIdx.x * blockDim.x + threadIdx.x;
    if (e >= NE) return;
    int s = ei[e];
    int d = ei[NE + e];
    int p = atomicAdd(&g_cursor[d], 1);
    g_src[p]  = s;
    g_norm[p] = g_dinv[s] * w[e] * g_dinv[d];
}

// ---------------- GEMM core: C = A @ W, tile 32 rows x 128 cols ----------------
template <int K>
__device__ __forceinline__ void gemm_body(const float* __restrict__ A,
                                          const float* __restrict__ W,
                                          float4& acc0, float4& acc1,
                                          float4& acc2, float4& acc3) {
    __shared__ float xs[32][64];
    __shared__ float Ws[64][128];
    int t    = threadIdx.x;
    int row0 = blockIdx.x * 32;
    int cg   = t & 31;
    int rg   = t >> 5;

    for (int kt = 0; kt < K; kt += 64) {
        const float4* Wg  = (const float4*)(W + kt * 128);
        float4*       Wsv = (float4*)Ws;
        #pragma unroll
        for (int idx = 0; idx < 8; idx++)
            Wsv[t + idx * 256] = Wg[t + idx * 256];
        #pragma unroll
        for (int idx = 0; idx < 8; idx++) {
            int li = t + idx * 256;
            int r = li >> 6, k = li & 63;
            int row = row0 + r;
            xs[r][k] = (row < NN) ? A[row * K + kt + k] : 0.f;
        }
        __syncthreads();

        #pragma unroll 8
        for (int k = 0; k < 64; k++) {
            float4 w4 = *(const float4*)&Ws[k][cg * 4];
            float x0 = xs[rg * 4 + 0][k];
            float x1 = xs[rg * 4 + 1][k];
            float x2 = xs[rg * 4 + 2][k];
            float x3 = xs[rg * 4 + 3][k];
            acc0.x += x0 * w4.x; acc0.y += x0 * w4.y; acc0.z += x0 * w4.z; acc0.w += x0 * w4.w;
            acc1.x += x1 * w4.x; acc1.y += x1 * w4.y; acc1.z += x1 * w4.z; acc1.w += x1 * w4.w;
            acc2.x += x2 * w4.x; acc2.y += x2 * w4.y; acc2.z += x2 * w4.z; acc2.w += x2 * w4.w;
            acc3.x += x3 * w4.x; acc3.y += x3 * w4.y; acc3.z += x3 * w4.z; acc3.w += x3 * w4.w;
        }
        __syncthreads();
    }
}

// input projection: g_h = relu(x @ W_in + b_in)
__global__ void __launch_bounds__(256)
gemm_in_kernel(const float* __restrict__ A, const float* __restrict__ W,
               const float* __restrict__ bias) {
    float4 acc0 = {0,0,0,0}, acc1 = {0,0,0,0}, acc2 = {0,0,0,0}, acc3 = {0,0,0,0};
    gemm_body<CIN>(A, W, acc0, acc1, acc2, acc3);

    int t = threadIdx.x, cg = t & 31, rg = t >> 5;
    int row0 = blockIdx.x * 32;
    float4 b4 = ((const float4*)bias)[cg];
    float4 accs[4] = {acc0, acc1, acc2, acc3};
    #pragma unroll
    for (int i = 0; i < 4; i++) {
        int row = row0 + rg * 4 + i;
        if (row < NN) {
            float4 v = accs[i];
            v.x = fmaxf(v.x + b4.x, 0.f); v.y = fmaxf(v.y + b4.y, 0.f);
            v.z = fmaxf(v.z + b4.z, 0.f); v.w = fmaxf(v.w + b4.w, 0.f);
            ((float4*)g_h)[row * 32 + cg] = v;
        }
    }
}

// hidden layer GEMM: g_m = g_h @ conv_W[l]
__global__ void __launch_bounds__(256)
gemm_hid_kernel(const float* __restrict__ W) {
    float4 acc0 = {0,0,0,0}, acc1 = {0,0,0,0}, acc2 = {0,0,0,0}, acc3 = {0,0,0,0};
    gemm_body<HID>(g_h, W, acc0, acc1, acc2, acc3);

    int t = threadIdx.x, cg = t & 31, rg = t >> 5;
    int row0 = blockIdx.x * 32;
    float4 accs[4] = {acc0, acc1, acc2, acc3};
    #pragma unroll
    for (int i = 0; i < 4; i++) {
        int row = row0 + rg * 4 + i;
        if (row < NN)
            ((float4*)g_m)[row * 32 + cg] = accs[i];
    }
}

// ---------------- fused aggregation + bias + LN + relu + residual ----------------
// one warp per node; 4 cols per lane (float4). last!=0 -> write to `out`
__global__ void __launch_bounds__(256)
agg_ln_kernel(const float* __restrict__ cb, const float* __restrict__ lg,
              const float* __restrict__ lb, float* __restrict__ out, int last) {
    int warp = threadIdx.x >> 5;
    int lane = threadIdx.x & 31;
    int i = blockIdx.x * 8 + warp;
    if (i >= NN) return;

    const float4* m4 = (const float4*)g_m;
    float di = g_dinv[i];
    float sn = di * di;                       // self-loop norm
    float4 acc = m4[i * 32 + lane];
    acc.x *= sn; acc.y *= sn; acc.z *= sn; acc.w *= sn;

    int jb = g_rowptr[i], je = g_rowptr[i + 1];
    int j = jb;
    // 2x unroll for memory-level parallelism
    for (; j + 2 <= je; j += 2) {
        int   s0 = g_src[j],     s1 = g_src[j + 1];
        float n0 = g_norm[j],    n1 = g_norm[j + 1];
        float4 v0 = m4[s0 * 32 + lane];
        float4 v1 = m4[s1 * 32 + lane];
        acc.x += n0 * v0.x + n1 * v1.x;
        acc.y += n0 * v0.y + n1 * v1.y;
        acc.z += n0 * v0.z + n1 * v1.z;
        acc.w += n0 * v0.w + n1 * v1.w;
    }
    if (j < je) {
        int   s  = g_src[j];
        float nw = g_norm[j];
        float4 v = m4[s * 32 + lane];
        acc.x += nw * v.x; acc.y += nw * v.y;
        acc.z += nw * v.z; acc.w += nw * v.w;
    }

    float4 b4 = ((const float4*)cb)[lane];
    acc.x += b4.x; acc.y += b4.y; acc.z += b4.z; acc.w += b4.w;

    float sum = acc.x + acc.y + acc.z + acc.w;
    #pragma unroll
    for (int o = 16; o; o >>= 1) sum += __shfl_xor_sync(0xFFFFFFFFu, sum, o);
    float mu = sum * (1.0f / 128.0f);

    float dx = acc.x - mu, dy = acc.y - mu, dz = acc.z - mu, dw = acc.w - mu;
    float vs = dx * dx + dy * dy + dz * dz + dw * dw;
    #pragma unroll
    for (int o = 16; o; o >>= 1) vs += __shfl_xor_sync(0xFFFFFFFFu, vs, o);
    float var = vs * (1.0f / 128.0f);
    float r = rsqrtf(var + LN_EPS);

    float4 g4  = ((const float4*)lg)[lane];
    float4 lb4 = ((const float4*)lb)[lane];
    float4 hres = ((const float4*)g_h)[i * 32 + lane];

    float4 o;
    o.x = fmaxf(dx * r * g4.x + lb4.x, 0.f) + hres.x;
    o.y = fmaxf(dy * r * g4.y + lb4.y, 0.f) + hres.y;
    o.z = fmaxf(dz * r * g4.z + lb4.z, 0.f) + hres.z;
    o.w = fmaxf(dw * r * g4.w + lb4.w, 0.f) + hres.w;

    if (last) ((float4*)out)[i * 32 + lane] = o;
    else      ((float4*)g_h)[i * 32 + lane] = o;
}

// ---------------- launch ----------------
extern "C" void kernel_launch(void* const* d_in, const int* in_sizes, int n_in,
                              void* d_out, int out_size) {
    const float* x      = (const float*)d_in[0];
    const int*   ei     = (const int*)d_in[1];      // int32 (JAX x64 disabled)
    const float* ew     = (const float*)d_in[2];
    const float* W_in   = (const float*)d_in[3];
    const float* b_in   = (const float*)d_in[4];
    const float* conv_W = (const float*)d_in[5];
    const float* conv_b = (const float*)d_in[6];
    const float* ln_g   = (const float*)d_in[7];
    const float* ln_b   = (const float*)d_in[8];
    float* out = (float*)d_out;

    const int TB = 256;
    int nb_n = (NN + TB - 1) / TB;
    int nb_e = (NE + TB - 1) / TB;

    // preprocessing: degree, dinv, CSR by dst
    init_kernel<<<nb_n, TB>>>();
    edge_deg_kernel<<<nb_e, TB>>>(ei, ew);
    dinv_kernel<<<nb_n, TB>>>();
    scan1_kernel<<<SCAN_NB, SCAN_BLK>>>();
    scan2_kernel<<<1, SCAN_BLK>>>();
    scan3_kernel<<<SCAN_NB, SCAN_BLK>>>();
    fill_kernel<<<nb_e, TB>>>(ei, ew);

    // input projection
    int gemm_blocks = (NN + 31) / 32;
    gemm_in_kernel<<<gemm_blocks, 256>>>(x, W_in, b_in);

    // layers
    int agg_blocks = (NN + 7) / 8;
    for (int l = 0; l < NL; l++) {
        gemm_hid_kernel<<<gemm_blocks, 256>>>(conv_W + l * HID * HID);
        agg_ln_kernel<<<agg_blocks, 256>>>(conv_b + l * HID, ln_g + l * HID,
                                           ln_b + l * HID, out, l == NL - 1);
    }
}

// round 5
// speedup vs baseline: 1.2407x; 1.0490x over previous
#include <cuda_runtime.h>
#include <cstdint>

#define NN   50000
#define NE   800000
#define CIN  64
#define HID  128
#define NL   4
#define LN_EPS 1e-5f

#define SCAN_BLK 256
#define SCAN_NB  ((NN + SCAN_BLK - 1) / SCAN_BLK)   // 196

// split-W storage: W_in (64*128) + 4 * (128*128), fragment-permuted
#define WSPLIT_TOTAL (CIN * HID + NL * HID * HID)   // 73728

// ---------------- scratch (no allocations allowed) ----------------
__device__ float g_h[NN * HID];
__device__ float g_m[NN * HID];
__device__ float g_deg[NN];
__device__ float g_dinv[NN];
__device__ int   g_count[NN];
__device__ int   g_rowptr[NN + 1];
__device__ int   g_cursor[NN];
__device__ int   g_src[NE];
__device__ float g_norm[NE];
__device__ int   g_bsum[SCAN_NB];
__device__ int   g_boff[SCAN_NB];
__device__ int   g_total;
__device__ float g_Whi[WSPLIT_TOTAL];
__device__ float g_Wlo[WSPLIT_TOTAL];

__device__ __forceinline__ float tf32_rn(float x) {
    uint32_t u;
    asm("cvt.rna.tf32.f32 %0, %1;" : "=r"(u) : "f"(x));
    return __uint_as_float(u);
}

// ---------------- preprocessing ----------------
__global__ void init_kernel() {
    int i = blockIdx.x * blockDim.x + threadIdx.x;
    if (i < NN) { g_deg[i] = 1.0f; g_count[i] = 0; }
}

__global__ void edge_deg_kernel(const int* __restrict__ ei,
                                const float* __restrict__ w) {
    int e = blockIdx.x * blockDim.x + threadIdx.x;
    if (e >= NE) return;
    int d = ei[NE + e];
    atomicAdd(&g_deg[d], w[e]);
    atomicAdd(&g_count[d], 1);
}

__global__ void dinv_kernel() {
    int i = blockIdx.x * blockDim.x + threadIdx.x;
    if (i < NN) {
        float dg = g_deg[i];
        g_dinv[i] = (dg > 0.f) ? rsqrtf(dg) : 0.f;
    }
}

__global__ void __launch_bounds__(SCAN_BLK)
scan1_kernel() {
    int b = blockIdx.x, t = threadIdx.x;
    int idx = b * SCAN_BLK + t;
    int v = (idx < NN) ? g_count[idx] : 0;
    int lane = t & 31, w = t >> 5;
    int x = v;
    #pragma unroll
    for (int o = 1; o < 32; o <<= 1) {
        int y = __shfl_up_sync(0xFFFFFFFFu, x, o);
        if (lane >= o) x += y;
    }
    __shared__ int wsum[8];
    if (lane == 31) wsum[w] = x;
    __syncthreads();
    if (w == 0 && lane < 8) {
        int s = wsum[lane];
        #pragma unroll
        for (int o = 1; o < 8; o <<= 1) {
            int y = __shfl_up_sync(0xFFu, s, o);
            if (lane >= o) s += y;
        }
        wsum[lane] = s;
    }
    __syncthreads();
    int incl = x + ((w > 0) ? wsum[w - 1] : 0);
    if (idx < NN) g_rowptr[idx] = incl - v;
    if (t == SCAN_BLK - 1) g_bsum[b] = incl;
}

__global__ void __launch_bounds__(SCAN_BLK)
scan2_kernel() {
    int t = threadIdx.x;
    int lane = t & 31, w = t >> 5;
    int v = (t < SCAN_NB) ? g_bsum[t] : 0;
    int x = v;
    #pragma unroll
    for (int o = 1; o < 32; o <<= 1) {
        int y = __shfl_up_sync(0xFFFFFFFFu, x, o);
        if (lane >= o) x += y;
    }
    __shared__ int wsum[8];
    if (lane == 31) wsum[w] = x;
    __syncthreads();
    if (w == 0 && lane < 8) {
        int s = wsum[lane];
        #pragma unroll
        for (int o = 1; o < 8; o <<= 1) {
            int y = __shfl_up_sync(0xFFu, s, o);
            if (lane >= o) s += y;
        }
        wsum[lane] = s;
    }
    __syncthreads();
    int incl = x + ((w > 0) ? wsum[w - 1] : 0);
    if (t < SCAN_NB) g_boff[t] = incl - v;
    if (t == SCAN_BLK - 1) g_total = incl;
}

__global__ void __launch_bounds__(SCAN_BLK)
scan3_kernel() {
    int idx = blockIdx.x * SCAN_BLK + threadIdx.x;
    if (idx < NN) {
        int r = g_rowptr[idx] + g_boff[idx >> 8];
        g_rowptr[idx] = r;
        g_cursor[idx] = r;
    }
    if (idx == 0) g_rowptr[NN] = g_total;
}

__global__ void fill_kernel(const int* __restrict__ ei,
                            const float* __restrict__ w) {
    int e = blockIdx.x * blockDim.x + threadIdx.x;
    if (e >= NE) return;
    int s = ei[e];
    int d = ei[NE + e];
    int p = atomicAdd(&g_cursor[d], 1);
    g_src[p]  = s;
    g_norm[p] = g_dinv[s] * w[e] * g_dinv[d];
}

// ---------------- W split into tf32 hi/lo, fragment-permuted layout ----------------
// For a K x 128 weight matrix, output pair index t -> (kk, ntile, lane):
//   t = (kk*16 + ntile)*32 + lane ; stores floats at [dstoff + 2t, dstoff + 2t + 1]
//   element r of pair: W[kk*8 + (lane&3) + r*4][ntile*8 + (lane>>2)]
__global__ void split_w_kernel(const float* __restrict__ W, int K, int dstoff) {
    int pairs = (K / 8) * 16 * 32;
    int t = blockIdx.x * blockDim.x + threadIdx.x;
    if (t >= pairs) return;
    int lane = t & 31, rest = t >> 5;
    int ntile = rest & 15, kk = rest >> 4;
    int k = kk * 8 + (lane & 3);
    int n = ntile * 8 + (lane >> 2);
    float a0 = W[k * 128 + n];
    float a1 = W[(k + 4) * 128 + n];
    float h0 = tf32_rn(a0), h1 = tf32_rn(a1);
    float l0 = tf32_rn(a0 - h0), l1 = tf32_rn(a1 - h1);
    int o = dstoff + t * 2;
    g_Whi[o] = h0; g_Whi[o + 1] = h1;
    g_Wlo[o] = l0; g_Wlo[o + 1] = l1;
}

// ---------------- tensor-core GEMM: C[N,128] = A[N,K] @ W[K,128] ----------------
__device__ __forceinline__ void mma_tf32(float c[4],
                                         uint32_t a0, uint32_t a1, uint32_t a2, uint32_t a3,
                                         uint32_t b0, uint32_t b1) {
    asm volatile(
        "mma.sync.aligned.m16n8k8.row.col.f32.tf32.tf32.f32 "
        "{%0,%1,%2,%3}, {%4,%5,%6,%7}, {%8,%9}, {%0,%1,%2,%3};"
        : "+f"(c[0]), "+f"(c[1]), "+f"(c[2]), "+f"(c[3])
        : "r"(a0), "r"(a1), "r"(a2), "r"(a3), "r"(b0), "r"(b1));
}

// block: 256 thr = 8 warps (4 along M x 2 along N); tile M=64, N=128; k-chunks of 32
template <int K>
__global__ void __launch_bounds__(256)
gemm_tc_kernel(const float* __restrict__ A, int woff,
               const float* __restrict__ bias, float* __restrict__ C, int relu) {
    constexpr int NK = K / 32;
    __shared__ float As[64][33];
    __shared__ float Bhi[4096];   // [4 kstep][16 ntile][32 lane][2]
    __shared__ float Blo[4096];

    int t = threadIdx.x, lane = t & 31, wid = t >> 5;
    int wm = wid & 3, wn = wid >> 2;
    int row0 = blockIdx.x * 64;
    int g = lane >> 2, tig = lane & 3;

    float c[8][4];
    #pragma unroll
    for (int i = 0; i < 8; i++)
        { c[i][0] = 0.f; c[i][1] = 0.f; c[i][2] = 0.f; c[i][3] = 0.f; }

    for (int kc = 0; kc < NK; kc++) {
        // stage A tile: 64 rows x 32 k (512 float4)
        #pragma unroll
        for (int i = 0; i < 2; i++) {
            int li = t + i * 256;
            int r = li >> 3, c4 = li & 7;
            float4 v = {0.f, 0.f, 0.f, 0.f};
            int row = row0 + r;
            if (row < NN) v = *(const float4*)(A + row * K + kc * 32 + c4 * 4);
            As[r][c4 * 4 + 0] = v.x; As[r][c4 * 4 + 1] = v.y;
            As[r][c4 * 4 + 2] = v.z; As[r][c4 * 4 + 3] = v.w;
        }
        // stage W fragments (coalesced, pre-permuted)
        const float4* srcH = (const float4*)(g_Whi + woff + kc * 4096);
        const float4* srcL = (const float4*)(g_Wlo + woff + kc * 4096);
        #pragma unroll
        for (int i = 0; i < 4; i++) {
            ((float4*)Bhi)[t + i * 256] = srcH[t + i * 256];
            ((float4*)Blo)[t + i * 256] = srcL[t + i * 256];
        }
        __syncthreads();

        #pragma unroll
        for (int ks = 0; ks < 4; ks++) {
            float ar0 = As[wm * 16 + g][ks * 8 + tig];
            float ar1 = As[wm * 16 + g + 8][ks * 8 + tig];
            float ar2 = As[wm * 16 + g][ks * 8 + tig + 4];
            float ar3 = As[wm * 16 + g + 8][ks * 8 + tig + 4];
            float ah0f = tf32_rn(ar0), ah1f = tf32_rn(ar1);
            float ah2f = tf32_rn(ar2), ah3f = tf32_rn(ar3);
            uint32_t ah0 = __float_as_uint(ah0f), ah1 = __float_as_uint(ah1f);
            uint32_t ah2 = __float_as_uint(ah2f), ah3 = __float_as_uint(ah3f);
            uint32_t al0 = __float_as_uint(tf32_rn(ar0 - ah0f));
            uint32_t al1 = __float_as_uint(tf32_rn(ar1 - ah1f));
            uint32_t al2 = __float_as_uint(tf32_rn(ar2 - ah2f));
            uint32_t al3 = __float_as_uint(tf32_rn(ar3 - ah3f));

            #pragma unroll
            for (int nt = 0; nt < 8; nt++) {
                int ntg = wn * 8 + nt;
                int bo = ((ks * 16 + ntg) * 32 + lane) * 2;
                float2 bh = *(const float2*)&Bhi[bo];
                float2 bl = *(const float2*)&Blo[bo];
                uint32_t bh0 = __float_as_uint(bh.x), bh1 = __float_as_uint(bh.y);
                uint32_t bl0 = __float_as_uint(bl.x), bl1 = __float_as_uint(bl.y);
                mma_tf32(c[nt], ah0, ah1, ah2, ah3, bh0, bh1);   // hi*hi
                mma_tf32(c[nt], ah0, ah1, ah2, ah3, bl0, bl1);   // hi*lo
                mma_tf32(c[nt], al0, al1, al2, al3, bh0, bh1);   // lo*hi
            }
        }
        __syncthreads();
    }

    // epilogue: c[nt][0..3] -> rows (row0+wm*16+g, +8), cols wn*64+nt*8+2*tig+{0,1}
    int r0 = row0 + wm * 16 + g;
    int r1 = r0 + 8;
    #pragma unroll
    for (int nt = 0; nt < 8; nt++) {
        int col = wn * 64 + nt * 8 + 2 * tig;
        float2 v0 = {c[nt][0], c[nt][1]};
        float2 v1 = {c[nt][2], c[nt][3]};
        if (bias) {
            float2 b2 = *(const float2*)(bias + col);
            v0.x += b2.x; v0.y += b2.y;
            v1.x += b2.x; v1.y += b2.y;
        }
        if (relu) {
            v0.x = fmaxf(v0.x, 0.f); v0.y = fmaxf(v0.y, 0.f);
            v1.x = fmaxf(v1.x, 0.f); v1.y = fmaxf(v1.y, 0.f);
        }
        if (r0 < NN) *(float2*)(C + r0 * 128 + col) = v0;
        if (r1 < NN) *(float2*)(C + r1 * 128 + col) = v1;
    }
}

// wrappers binding device-global pointers (cannot take addr of __device__ on host)
__global__ void __launch_bounds__(256)
gemm_in_tc(const float* __restrict__ x, const float* __restrict__ bias) {
    // delegate via inline body: implemented below through a direct call trick
}

// ---------------- fused aggregation + bias + LN + relu + residual ----------------
__global__ void __launch_bounds__(256)
agg_ln_kernel(const float* __restrict__ cb, const float* __restrict__ lg,
              const float* __restrict__ lb, float* __restrict__ out, int last) {
    int warp = threadIdx.x >> 5;
    int lane = threadIdx.x & 31;
    int i = blockIdx.x * 8 + warp;
    if (i >= NN) return;

    const float4* m4 = (const float4*)g_m;
    float di = g_dinv[i];
    float sn = di * di;
    float4 acc = m4[i * 32 + lane];
    acc.x *= sn; acc.y *= sn; acc.z *= sn; acc.w *= sn;

    int jb = g_rowptr[i], je = g_rowptr[i + 1];
    int j = jb;
    for (; j + 2 <= je; j += 2) {
        int   s0 = g_src[j],  s1 = g_src[j + 1];
        float n0 = g_norm[j], n1 = g_norm[j + 1];
        float4 v0 = m4[s0 * 32 + lane];
        float4 v1 = m4[s1 * 32 + lane];
        acc.x += n0 * v0.x + n1 * v1.x;
        acc.y += n0 * v0.y + n1 * v1.y;
        acc.z += n0 * v0.z + n1 * v1.z;
        acc.w += n0 * v0.w + n1 * v1.w;
    }
    if (j < je) {
        int   s  = g_src[j];
        float nw = g_norm[j];
        float4 v = m4[s * 32 + lane];
        acc.x += nw * v.x; acc.y += nw * v.y;
        acc.z += nw * v.z; acc.w += nw * v.w;
    }

    float4 b4 = ((const float4*)cb)[lane];
    acc.x += b4.x; acc.y += b4.y; acc.z += b4.z; acc.w += b4.w;

    float sum = acc.x + acc.y + acc.z + acc.w;
    #pragma unroll
    for (int o = 16; o; o >>= 1) sum += __shfl_xor_sync(0xFFFFFFFFu, sum, o);
    float mu = sum * (1.0f / 128.0f);

    float dx = acc.x - mu, dy = acc.y - mu, dz = acc.z - mu, dw = acc.w - mu;
    float vs = dx * dx + dy * dy + dz * dz + dw * dw;
    #pragma unroll
    for (int o = 16; o; o >>= 1) vs += __shfl_xor_sync(0xFFFFFFFFu, vs, o);
    float var = vs * (1.0f / 128.0f);
    float r = rsqrtf(var + LN_EPS);

    float4 g4  = ((const float4*)lg)[lane];
    float4 lb4 = ((const float4*)lb)[lane];
    float4 hres = ((const float4*)g_h)[i * 32 + lane];

    float4 o;
    o.x = fmaxf(dx * r * g4.x + lb4.x, 0.f) + hres.x;
    o.y = fmaxf(dy * r * g4.y + lb4.y, 0.f) + hres.y;
    o.z = fmaxf(dz * r * g4.z + lb4.z, 0.f) + hres.z;
    o.w = fmaxf(dw * r * g4.w + lb4.w, 0.f) + hres.w;

    if (last) ((float4*)out)[i * 32 + lane] = o;
    else      ((float4*)g_h)[i * 32 + lane] = o;
}

// kernels that bind device-global A/C operands for the templated GEMM
__global__ void __launch_bounds__(256)
gemm_in_kernel_tc(const float* __restrict__ x, const float* __restrict__ bias);
__global__ void __launch_bounds__(256)
gemm_hid_kernel_tc(int woff);

// Implement by forwarding into a device inline (template instantiation per K)
template <int K>
__device__ __forceinline__ void gemm_tc_body(const float* __restrict__ A, int woff,
                                             const float* __restrict__ bias,
                                             float* __restrict__ C, int relu);

// NOTE: simplest correct approach — duplicate the kernel body via the template
// as a __device__ function called from two thin __global__ wrappers.
template <int K>
__device__ __forceinline__ void gemm_tc_body(const float* __restrict__ A, int woff,
                                             const float* __restrict__ bias,
                                             float* __restrict__ C, int relu) {
    constexpr int NK = K / 32;
    __shared__ float As[64][33];
    __shared__ float Bhi[4096];
    __shared__ float Blo[4096];

    int t = threadIdx.x, lane = t & 31, wid = t >> 5;
    int wm = wid & 3, wn = wid >> 2;
    int row0 = blockIdx.x * 64;
    int g = lane >> 2, tig = lane & 3;

    float c[8][4];
    #pragma unroll
    for (int i = 0; i < 8; i++)
        { c[i][0] = 0.f; c[i][1] = 0.f; c[i][2] = 0.f; c[i][3] = 0.f; }

    for (int kc = 0; kc < NK; kc++) {
        #pragma unroll
        for (int i = 0; i < 2; i++) {
            int li = t + i * 256;
            int r = li >> 3, c4 = li & 7;
            float4 v = {0.f, 0.f, 0.f, 0.f};
            int row = row0 + r;
            if (row < NN) v = *(const float4*)(A + row * K + kc * 32 + c4 * 4);
            As[r][c4 * 4 + 0] = v.x; As[r][c4 * 4 + 1] = v.y;
            As[r][c4 * 4 + 2] = v.z; As[r][c4 * 4 + 3] = v.w;
        }
        const float4* srcH = (const float4*)(g_Whi + woff + kc * 4096);
        const float4* srcL = (const float4*)(g_Wlo + woff + kc * 4096);
        #pragma unroll
        for (int i = 0; i < 4; i++) {
            ((float4*)Bhi)[t + i * 256] = srcH[t + i * 256];
            ((float4*)Blo)[t + i * 256] = srcL[t + i * 256];
        }
        __syncthreads();

        #pragma unroll
        for (int ks = 0; ks < 4; ks++) {
            float ar0 = As[wm * 16 + g][ks * 8 + tig];
            float ar1 = As[wm * 16 + g + 8][ks * 8 + tig];
            float ar2 = As[wm * 16 + g][ks * 8 + tig + 4];
            float ar3 = As[wm * 16 + g + 8][ks * 8 + tig + 4];
            float ah0f = tf32_rn(ar0), ah1f = tf32_rn(ar1);
            float ah2f = tf32_rn(ar2), ah3f = tf32_rn(ar3);
            uint32_t ah0 = __float_as_uint(ah0f), ah1 = __float_as_uint(ah1f);
            uint32_t ah2 = __float_as_uint(ah2f), ah3 = __float_as_uint(ah3f);
            uint32_t al0 = __float_as_uint(tf32_rn(ar0 - ah0f));
            uint32_t al1 = __float_as_uint(tf32_rn(ar1 - ah1f));
            uint32_t al2 = __float_as_uint(tf32_rn(ar2 - ah2f));
            uint32_t al3 = __float_as_uint(tf32_rn(ar3 - ah3f));

            #pragma unroll
            for (int nt = 0; nt < 8; nt++) {
                int ntg = wn * 8 + nt;
                int bo = ((ks * 16 + ntg) * 32 + lane) * 2;
                float2 bh = *(const float2*)&Bhi[bo];
                float2 bl = *(const float2*)&Blo[bo];
                uint32_t bh0 = __float_as_uint(bh.x), bh1 = __float_as_uint(bh.y);
                uint32_t bl0 = __float_as_uint(bl.x), bl1 = __float_as_uint(bl.y);
                mma_tf32(c[nt], ah0, ah1, ah2, ah3, bh0, bh1);
                mma_tf32(c[nt], ah0, ah1, ah2, ah3, bl0, bl1);
                mma_tf32(c[nt], al0, al1, al2, al3, bh0, bh1);
            }
        }
        __syncthreads();
    }

    int r0 = row0 + wm * 16 + g;
    int r1 = r0 + 8;
    #pragma unroll
    for (int nt = 0; nt < 8; nt++) {
        int col = wn * 64 + nt * 8 + 2 * tig;
        float2 v0 = {c[nt][0], c[nt][1]};
        float2 v1 = {c[nt][2], c[nt][3]};
        if (bias) {
            float2 b2 = *(const float2*)(bias + col);
            v0.x += b2.x; v0.y += b2.y;
            v1.x += b2.x; v1.y += b2.y;
        }
        if (relu) {
            v0.x = fmaxf(v0.x, 0.f); v0.y = fmaxf(v0.y, 0.f);
            v1.x = fmaxf(v1.x, 0.f); v1.y = fmaxf(v1.y, 0.f);
        }
        if (r0 < NN) *(float2*)(C + r0 * 128 + col) = v0;
        if (r1 < NN) *(float2*)(C + r1 * 128 + col) = v1;
    }
}

__global__ void __launch_bounds__(256)
gemm_in_kernel_tc(const float* __restrict__ x, const float* __restrict__ bias) {
    gemm_tc_body<CIN>(x, 0, bias, g_h, 1);
}

__global__ void __launch_bounds__(256)
gemm_hid_kernel_tc(int woff) {
    gemm_tc_body<HID>(g_h, woff, nullptr, g_m, 0);
}

// ---------------- launch ----------------
extern "C" void kernel_launch(void* const* d_in, const int* in_sizes, int n_in,
                              void* d_out, int out_size) {
    const float* x      = (const float*)d_in[0];
    const int*   ei     = (const int*)d_in[1];
    const float* ew     = (const float*)d_in[2];
    const float* W_in   = (const float*)d_in[3];
    const float* b_in   = (const float*)d_in[4];
    const float* conv_W = (const float*)d_in[5];
    const float* conv_b = (const float*)d_in[6];
    const float* ln_g   = (const float*)d_in[7];
    const float* ln_b   = (const float*)d_in[8];
    float* out = (float*)d_out;

    const int TB = 256;
    int nb_n = (NN + TB - 1) / TB;
    int nb_e = (NE + TB - 1) / TB;

    // preprocessing: degree, dinv, CSR by dst
    init_kernel<<<nb_n, TB>>>();
    edge_deg_kernel<<<nb_e, TB>>>(ei, ew);
    dinv_kernel<<<nb_n, TB>>>();
    scan1_kernel<<<SCAN_NB, SCAN_BLK>>>();
    scan2_kernel<<<1, SCAN_BLK>>>();
    scan3_kernel<<<SCAN_NB, SCAN_BLK>>>();
    fill_kernel<<<nb_e, TB>>>(ei, ew);

    // split weights (tf32 hi/lo, permuted fragment layout)
    split_w_kernel<<<(CIN * HID / 2 + TB - 1) / TB, TB>>>(W_in, CIN, 0);
    for (int l = 0; l < NL; l++)
        split_w_kernel<<<(HID * HID / 2 + TB - 1) / TB, TB>>>(
            conv_W + l * HID * HID, HID, CIN * HID + l * HID * HID);

    // input projection (tensor core)
    int gemm_blocks = (NN + 63) / 64;
    gemm_in_kernel_tc<<<gemm_blocks, 256>>>(x, b_in);

    // layers
    int agg_blocks = (NN + 7) / 8;
    for (int l = 0; l < NL; l++) {
        gemm_hid_kernel_tc<<<gemm_blocks, 256>>>(CIN * HID + l * HID * HID);
        agg_ln_kernel<<<agg_blocks, 256>>>(conv_b + l * HID, ln_g + l * HID,
                                           ln_b + l * HID, out, l == NL - 1);
    }
}

// round 6
// speedup vs baseline: 1.5801x; 1.2735x over previous
#include <cuda_runtime.h>
#include <cuda_bf16.h>
#include <cstdint>

#define NN   50000
#define NE   800000
#define CIN  64
#define HID  128
#define NL   4
#define LN_EPS 1e-5f

#define SCAN_BLK 256
#define SCAN_NB  ((NN + SCAN_BLK - 1) / SCAN_BLK)   // 196

// split-W storage (u32 = packed bf16x2 along k): K*64 u32 per K x 128 matrix
#define W_U32_TOTAL (CIN * 64 + NL * HID * 64)      // 4096 + 32768 = 36864

// ---------------- scratch (no allocations allowed) ----------------
__device__ float    g_h[NN * HID];
__device__ float    g_m[NN * HID];
__device__ float    g_deg[NN];
__device__ float    g_dinv[NN];
__device__ int      g_count[NN];
__device__ int      g_rowptr[NN + 1];
__device__ int      g_cursor[NN];
__device__ int      g_src[NE];
__device__ float    g_norm[NE];
__device__ int      g_bsum[SCAN_NB];
__device__ int      g_boff[SCAN_NB];
__device__ int      g_total;
__device__ uint32_t g_Whi[W_U32_TOTAL];
__device__ uint32_t g_Wlo[W_U32_TOTAL];

// split a float2 into packed bf16x2 hi + bf16x2 lo(residual)
__device__ __forceinline__ void bsplit2(float2 v, uint32_t& hi, uint32_t& lo) {
    __nv_bfloat162 h = __float22bfloat162_rn(v);
    float2 hf = __bfloat1622float2(h);
    float2 r = make_float2(v.x - hf.x, v.y - hf.y);
    __nv_bfloat162 l = __float22bfloat162_rn(r);
    hi = *(uint32_t*)&h;
    lo = *(uint32_t*)&l;
}

// ---------------- preprocessing ----------------
__global__ void init_kernel() {
    int i = blockIdx.x * blockDim.x + threadIdx.x;
    if (i < NN) { g_deg[i] = 1.0f; g_count[i] = 0; }
}

__global__ void edge_deg_kernel(const int* __restrict__ ei,
                                const float* __restrict__ w) {
    int e = blockIdx.x * blockDim.x + threadIdx.x;
    if (e >= NE) return;
    int d = ei[NE + e];
    atomicAdd(&g_deg[d], w[e]);
    atomicAdd(&g_count[d], 1);
}

__global__ void dinv_kernel() {
    int i = blockIdx.x * blockDim.x + threadIdx.x;
    if (i < NN) {
        float dg = g_deg[i];
        g_dinv[i] = (dg > 0.f) ? rsqrtf(dg) : 0.f;
    }
}

__global__ void __launch_bounds__(SCAN_BLK)
scan1_kernel() {
    int b = blockIdx.x, t = threadIdx.x;
    int idx = b * SCAN_BLK + t;
    int v = (idx < NN) ? g_count[idx] : 0;
    int lane = t & 31, w = t >> 5;
    int x = v;
    #pragma unroll
    for (int o = 1; o < 32; o <<= 1) {
        int y = __shfl_up_sync(0xFFFFFFFFu, x, o);
        if (lane >= o) x += y;
    }
    __shared__ int wsum[8];
    if (lane == 31) wsum[w] = x;
    __syncthreads();
    if (w == 0 && lane < 8) {
        int s = wsum[lane];
        #pragma unroll
        for (int o = 1; o < 8; o <<= 1) {
            int y = __shfl_up_sync(0xFFu, s, o);
            if (lane >= o) s += y;
        }
        wsum[lane] = s;
    }
    __syncthreads();
    int incl = x + ((w > 0) ? wsum[w - 1] : 0);
    if (idx < NN) g_rowptr[idx] = incl - v;
    if (t == SCAN_BLK - 1) g_bsum[b] = incl;
}

__global__ void __launch_bounds__(SCAN_BLK)
scan2_kernel() {
    int t = threadIdx.x;
    int lane = t & 31, w = t >> 5;
    int v = (t < SCAN_NB) ? g_bsum[t] : 0;
    int x = v;
    #pragma unroll
    for (int o = 1; o < 32; o <<= 1) {
        int y = __shfl_up_sync(0xFFFFFFFFu, x, o);
        if (lane >= o) x += y;
    }
    __shared__ int wsum[8];
    if (lane == 31) wsum[w] = x;
    __syncthreads();
    if (w == 0 && lane < 8) {
        int s = wsum[lane];
        #pragma unroll
        for (int o = 1; o < 8; o <<= 1) {
            int y = __shfl_up_sync(0xFFu, s, o);
            if (lane >= o) s += y;
        }
        wsum[lane] = s;
    }
    __syncthreads();
    int incl = x + ((w > 0) ? wsum[w - 1] : 0);
    if (t < SCAN_NB) g_boff[t] = incl - v;
    if (t == SCAN_BLK - 1) g_total = incl;
}

__global__ void __launch_bounds__(SCAN_BLK)
scan3_kernel() {
    int idx = blockIdx.x * SCAN_BLK + threadIdx.x;
    if (idx < NN) {
        int r = g_rowptr[idx] + g_boff[idx >> 8];
        g_rowptr[idx] = r;
        g_cursor[idx] = r;
    }
    if (idx == 0) g_rowptr[NN] = g_total;
}

__global__ void fill_kernel(const int* __restrict__ ei,
                            const float* __restrict__ w) {
    int e = blockIdx.x * blockDim.x + threadIdx.x;
    if (e >= NE) return;
    int s = ei[e];
    int d = ei[NE + e];
    int p = atomicAdd(&g_cursor[d], 1);
    g_src[p]  = s;
    g_norm[p] = g_dinv[s] * w[e] * g_dinv[d];
}

// ---------------- W split into bf16 hi/lo, mma-fragment-permuted ----------------
// u32 index u: r=u&1, lane=(u>>1)&31, ntile=(u>>6)&15, ks=u>>10
//   g=lane>>2, tig=lane&3; k0 = ks*16 + 2*tig + r*8; n = ntile*8 + g
//   u32 = pack(bf16 W[k0][n] (lo half), bf16 W[k0+1][n] (hi half))
__global__ void split_w_kernel(const float* __restrict__ W, int K, int dstoff) {
    int tot = K * 64;
    int u = blockIdx.x * blockDim.x + threadIdx.x;
    if (u >= tot) return;
    int r = u & 1, lane = (u >> 1) & 31, ntile = (u >> 6) & 15, ks = u >> 10;
    int g = lane >> 2, tig = lane & 3;
    int k0 = ks * 16 + 2 * tig + r * 8;
    int n  = ntile * 8 + g;
    float2 v = make_float2(W[k0 * 128 + n], W[(k0 + 1) * 128 + n]);
    uint32_t hi, lo;
    bsplit2(v, hi, lo);
    g_Whi[dstoff + u] = hi;
    g_Wlo[dstoff + u] = lo;
}

// ---------------- bf16 split tensor-core GEMM: C[N,128] = A[N,K] @ W[K,128] ----
__device__ __forceinline__ void mma_bf16(float c[4],
                                         uint32_t a0, uint32_t a1, uint32_t a2, uint32_t a3,
                                         uint32_t b0, uint32_t b1) {
    asm volatile(
        "mma.sync.aligned.m16n8k16.row.col.f32.bf16.bf16.f32 "
        "{%0,%1,%2,%3}, {%4,%5,%6,%7}, {%8,%9}, {%0,%1,%2,%3};"
        : "+f"(c[0]), "+f"(c[1]), "+f"(c[2]), "+f"(c[3])
        : "r"(a0), "r"(a1), "r"(a2), "r"(a3), "r"(b0), "r"(b1));
}

// block: 256 thr = 8 warps (4 M x 2 N); tile M=64, N=128; k-chunks of 32
template <int K>
__device__ __forceinline__ void gemm_tc_body(const float* __restrict__ A, int woff,
                                             const float* __restrict__ bias,
                                             float* __restrict__ C, int relu) {
    constexpr int NK = K / 32;
    __shared__ float    As[64 * 40];          // stride 40 -> 2-way max conflicts
    __shared__ uint32_t Bhi[2048];            // [2 ks][16 ntile][32 lane][2]
    __shared__ uint32_t Blo[2048];

    int t = threadIdx.x, lane = t & 31, wid = t >> 5;
    int wm = wid & 3, wn = wid >> 2;
    int row0 = blockIdx.x * 64;
    int g = lane >> 2, tig = lane & 3;

    float c[8][4];
    #pragma unroll
    for (int i = 0; i < 8; i++)
        { c[i][0] = 0.f; c[i][1] = 0.f; c[i][2] = 0.f; c[i][3] = 0.f; }

    for (int kc = 0; kc < NK; kc++) {
        // stage A tile: 64 rows x 32 k, fp32, padded stride 40
        #pragma unroll
        for (int i = 0; i < 2; i++) {
            int li = t + i * 256;
            int r = li >> 3, c4 = li & 7;
            float4 v = {0.f, 0.f, 0.f, 0.f};
            int row = row0 + r;
            if (row < NN) v = *(const float4*)(A + row * K + kc * 32 + c4 * 4);
            *(float4*)&As[r * 40 + c4 * 4] = v;
        }
        // stage W fragments (pre-permuted packed bf16x2): 2048 u32 each
        const uint4* srcH = (const uint4*)(g_Whi + woff + kc * 2048);
        const uint4* srcL = (const uint4*)(g_Wlo + woff + kc * 2048);
        #pragma unroll
        for (int i = 0; i < 2; i++) {
            ((uint4*)Bhi)[t + i * 256] = srcH[t + i * 256];
            ((uint4*)Blo)[t + i * 256] = srcL[t + i * 256];
        }
        __syncthreads();

        #pragma unroll
        for (int ks = 0; ks < 2; ks++) {
            int kb   = ks * 16 + 2 * tig;
            int rowa = wm * 16 + g;
            float2 p0 = *(const float2*)&As[rowa * 40 + kb];
            float2 p1 = *(const float2*)&As[(rowa + 8) * 40 + kb];
            float2 p2 = *(const float2*)&As[rowa * 40 + kb + 8];
            float2 p3 = *(const float2*)&As[(rowa + 8) * 40 + kb + 8];
            uint32_t ah0, ah1, ah2, ah3, al0, al1, al2, al3;
            bsplit2(p0, ah0, al0);
            bsplit2(p1, ah1, al1);
            bsplit2(p2, ah2, al2);
            bsplit2(p3, ah3, al3);

            #pragma unroll
            for (int nt = 0; nt < 8; nt++) {
                int ntg = wn * 8 + nt;
                int bo = ((ks * 16 + ntg) * 32 + lane) * 2;
                uint2 bh = *(const uint2*)&Bhi[bo];
                uint2 bl = *(const uint2*)&Blo[bo];
                mma_bf16(c[nt], ah0, ah1, ah2, ah3, bh.x, bh.y);   // hi*hi
                mma_bf16(c[nt], ah0, ah1, ah2, ah3, bl.x, bl.y);   // hi*lo
                mma_bf16(c[nt], al0, al1, al2, al3, bh.x, bh.y);   // lo*hi
            }
        }
        __syncthreads();
    }

    // epilogue: c[nt][0..3] -> rows (row0+wm*16+g, +8), cols wn*64+nt*8+2*tig+{0,1}
    int r0 = row0 + wm * 16 + g;
    int r1 = r0 + 8;
    #pragma unroll
    for (int nt = 0; nt < 8; nt++) {
        int col = wn * 64 + nt * 8 + 2 * tig;
        float2 v0 = {c[nt][0], c[nt][1]};
        float2 v1 = {c[nt][2], c[nt][3]};
        if (bias) {
            float2 b2 = *(const float2*)(bias + col);
            v0.x += b2.x; v0.y += b2.y;
            v1.x += b2.x; v1.y += b2.y;
        }
        if (relu) {
            v0.x = fmaxf(v0.x, 0.f); v0.y = fmaxf(v0.y, 0.f);
            v1.x = fmaxf(v1.x, 0.f); v1.y = fmaxf(v1.y, 0.f);
        }
        if (r0 < NN) *(float2*)(C + r0 * 128 + col) = v0;
        if (r1 < NN) *(float2*)(C + r1 * 128 + col) = v1;
    }
}

__global__ void __launch_bounds__(256)
gemm_in_kernel_tc(const float* __restrict__ x, const float* __restrict__ bias) {
    gemm_tc_body<CIN>(x, 0, bias, g_h, 1);
}

__global__ void __launch_bounds__(256)
gemm_hid_kernel_tc(int woff) {
    gemm_tc_body<HID>(g_h, woff, nullptr, g_m, 0);
}

// ---------------- fused aggregation + bias + LN + relu + residual ----------------
__global__ void __launch_bounds__(256)
agg_ln_kernel(const float* __restrict__ cb, const float* __restrict__ lg,
              const float* __restrict__ lb, float* __restrict__ out, int last) {
    int warp = threadIdx.x >> 5;
    int lane = threadIdx.x & 31;
    int i = blockIdx.x * 8 + warp;
    if (i >= NN) return;

    const float4* m4 = (const float4*)g_m;
    float di = g_dinv[i];
    float sn = di * di;
    float4 acc = m4[i * 32 + lane];
    acc.x *= sn; acc.y *= sn; acc.z *= sn; acc.w *= sn;

    int jb = g_rowptr[i], je = g_rowptr[i + 1];
    int j = jb;
    for (; j + 2 <= je; j += 2) {
        int   s0 = g_src[j],  s1 = g_src[j + 1];
        float n0 = g_norm[j], n1 = g_norm[j + 1];
        float4 v0 = m4[s0 * 32 + lane];
        float4 v1 = m4[s1 * 32 + lane];
        acc.x += n0 * v0.x + n1 * v1.x;
        acc.y += n0 * v0.y + n1 * v1.y;
        acc.z += n0 * v0.z + n1 * v1.z;
        acc.w += n0 * v0.w + n1 * v1.w;
    }
    if (j < je) {
        int   s  = g_src[j];
        float nw = g_norm[j];
        float4 v = m4[s * 32 + lane];
        acc.x += nw * v.x; acc.y += nw * v.y;
        acc.z += nw * v.z; acc.w += nw * v.w;
    }

    float4 b4 = ((const float4*)cb)[lane];
    acc.x += b4.x; acc.y += b4.y; acc.z += b4.z; acc.w += b4.w;

    float sum = acc.x + acc.y + acc.z + acc.w;
    #pragma unroll
    for (int o = 16; o; o >>= 1) sum += __shfl_xor_sync(0xFFFFFFFFu, sum, o);
    float mu = sum * (1.0f / 128.0f);

    float dx = acc.x - mu, dy = acc.y - mu, dz = acc.z - mu, dw = acc.w - mu;
    float vs = dx * dx + dy * dy + dz * dz + dw * dw;
    #pragma unroll
    for (int o = 16; o; o >>= 1) vs += __shfl_xor_sync(0xFFFFFFFFu, vs, o);
    float var = vs * (1.0f / 128.0f);
    float r = rsqrtf(var + LN_EPS);

    float4 g4  = ((const float4*)lg)[lane];
    float4 lb4 = ((const float4*)lb)[lane];
    float4 hres = ((const float4*)g_h)[i * 32 + lane];

    float4 o;
    o.x = fmaxf(dx * r * g4.x + lb4.x, 0.f) + hres.x;
    o.y = fmaxf(dy * r * g4.y + lb4.y, 0.f) + hres.y;
    o.z = fmaxf(dz * r * g4.z + lb4.z, 0.f) + hres.z;
    o.w = fmaxf(dw * r * g4.w + lb4.w, 0.f) + hres.w;

    if (last) ((float4*)out)[i * 32 + lane] = o;
    else      ((float4*)g_h)[i * 32 + lane] = o;
}

// ---------------- launch ----------------
extern "C" void kernel_launch(void* const* d_in, const int* in_sizes, int n_in,
                              void* d_out, int out_size) {
    const float* x      = (const float*)d_in[0];
    const int*   ei     = (const int*)d_in[1];
    const float* ew     = (const float*)d_in[2];
    const float* W_in   = (const float*)d_in[3];
    const float* b_in   = (const float*)d_in[4];
    const float* conv_W = (const float*)d_in[5];
    const float* conv_b = (const float*)d_in[6];
    const float* ln_g   = (const float*)d_in[7];
    const float* ln_b   = (const float*)d_in[8];
    float* out = (float*)d_out;

    const int TB = 256;
    int nb_n = (NN + TB - 1) / TB;
    int nb_e = (NE + TB - 1) / TB;

    // preprocessing: degree, dinv, CSR by dst
    init_kernel<<<nb_n, TB>>>();
    edge_deg_kernel<<<nb_e, TB>>>(ei, ew);
    dinv_kernel<<<nb_n, TB>>>();
    scan1_kernel<<<SCAN_NB, SCAN_BLK>>>();
    scan2_kernel<<<1, SCAN_BLK>>>();
    scan3_kernel<<<SCAN_NB, SCAN_BLK>>>();
    fill_kernel<<<nb_e, TB>>>(ei, ew);

    // split weights (bf16 hi/lo, permuted fragment layout)
    split_w_kernel<<<(CIN * 64 + TB - 1) / TB, TB>>>(W_in, CIN, 0);
    for (int l = 0; l < NL; l++)
        split_w_kernel<<<(HID * 64 + TB - 1) / TB, TB>>>(
            conv_W + l * HID * HID, HID, CIN * 64 + l * HID * 64);

    // input projection (tensor core)
    int gemm_blocks = (NN + 63) / 64;
    gemm_in_kernel_tc<<<gemm_blocks, 256>>>(x, b_in);

    // layers
    int agg_blocks = (NN + 7) / 8;
    for (int l = 0; l < NL; l++) {
        gemm_hid_kernel_tc<<<gemm_blocks, 256>>>(CIN * 64 + l * HID * 64);
        agg_ln_kernel<<<agg_blocks, 256>>>(conv_b + l * HID, ln_g + l * HID,
                                           ln_b + l * HID, out, l == NL - 1);
    }
}